// round 1
// baseline (speedup 1.0000x reference)
#include <cuda_runtime.h>
#include <cuda_bf16.h>
#include <cstdint>

// Problem constants
#define BATCH 16
#define HH 56
#define WW 56
#define NN (HH * WW)          // 3136
#define CC 384
#define C3 (3 * CC)           // 1152
#define NHEADS 12
#define HD 32
#define WSZ 7
#define WIN 49
#define MROWS (BATCH * NN)    // 50176

// Scratch (allocation-free rule: __device__ globals)
__device__ float g_qkv[(size_t)MROWS * C3];   // 231 MB
__device__ float g_y[(size_t)MROWS * CC];     // 77 MB

// ---------------------------------------------------------------------------
// SGEMM: C[M,N] = A[M,K] @ B[K,N] (+bias). 128x128 tile, BK=8, 8x8 per thread,
// double-buffered smem, split-64 conflict-free layout. M%128==0, N%128==0, K%8==0.
// ---------------------------------------------------------------------------
__global__ __launch_bounds__(256) void sgemm_kernel(
    const float* __restrict__ A, const float* __restrict__ B,
    float* __restrict__ C, const float* __restrict__ bias,
    int M, int N, int K)
{
    __shared__ float As[2][8][128];
    __shared__ float Bs[2][8][128];

    const int tid = threadIdx.x;
    const int tx = tid & 15;     // 0..15 column group
    const int ty = tid >> 4;     // 0..15 row group

    const size_t mbase = (size_t)blockIdx.y * 128;
    const int    nbase = blockIdx.x * 128;

    const float* Ag = A + mbase * (size_t)K;
    const float* Bg = B + nbase;

    const int arow = tid >> 1;          // 0..127
    const int acol = (tid & 1) << 2;    // 0 or 4
    const int brow = tid >> 5;          // 0..7
    const int bcol = (tid & 31) << 2;   // 0..124

    float acc[8][8];
#pragma unroll
    for (int i = 0; i < 8; i++)
#pragma unroll
        for (int j = 0; j < 8; j++) acc[i][j] = 0.f;

    float4 a4 = *(const float4*)(Ag + (size_t)arow * K + acol);
    float4 b4 = *(const float4*)(Bg + (size_t)brow * N + bcol);
    As[0][acol + 0][arow] = a4.x; As[0][acol + 1][arow] = a4.y;
    As[0][acol + 2][arow] = a4.z; As[0][acol + 3][arow] = a4.w;
    *(float4*)&Bs[0][brow][bcol] = b4;
    __syncthreads();

    int buf = 0;
    for (int k0 = 8; k0 <= K; k0 += 8) {
        if (k0 < K) {
            a4 = *(const float4*)(Ag + (size_t)arow * K + k0 + acol);
            b4 = *(const float4*)(Bg + (size_t)(k0 + brow) * N + bcol);
        }
#pragma unroll
        for (int kk = 0; kk < 8; kk++) {
            float4 a0 = *(const float4*)&As[buf][kk][ty * 4];
            float4 a1 = *(const float4*)&As[buf][kk][64 + ty * 4];
            float4 b0 = *(const float4*)&Bs[buf][kk][tx * 4];
            float4 b1 = *(const float4*)&Bs[buf][kk][64 + tx * 4];
            float ar[8] = {a0.x, a0.y, a0.z, a0.w, a1.x, a1.y, a1.z, a1.w};
            float br[8] = {b0.x, b0.y, b0.z, b0.w, b1.x, b1.y, b1.z, b1.w};
#pragma unroll
            for (int i = 0; i < 8; i++)
#pragma unroll
                for (int j = 0; j < 8; j++)
                    acc[i][j] += ar[i] * br[j];
        }
        buf ^= 1;
        if (k0 < K) {
            As[buf][acol + 0][arow] = a4.x; As[buf][acol + 1][arow] = a4.y;
            As[buf][acol + 2][arow] = a4.z; As[buf][acol + 3][arow] = a4.w;
            *(float4*)&Bs[buf][brow][bcol] = b4;
        }
        __syncthreads();
    }

    // Epilogue: rows {ty*4+ii, 64+ty*4+ii}, cols {tx*4+jj, 64+tx*4+jj}
#pragma unroll
    for (int ih = 0; ih < 2; ih++) {
#pragma unroll
        for (int ii = 0; ii < 4; ii++) {
            int row = ih * 64 + ty * 4 + ii;
            float* Crow = C + (mbase + row) * (size_t)N + nbase;
#pragma unroll
            for (int jh = 0; jh < 2; jh++) {
                int col = jh * 64 + tx * 4;
                float4 r;
                r.x = acc[ih * 4 + ii][jh * 4 + 0];
                r.y = acc[ih * 4 + ii][jh * 4 + 1];
                r.z = acc[ih * 4 + ii][jh * 4 + 2];
                r.w = acc[ih * 4 + ii][jh * 4 + 3];
                if (bias) {
                    r.x += bias[nbase + col + 0];
                    r.y += bias[nbase + col + 1];
                    r.z += bias[nbase + col + 2];
                    r.w += bias[nbase + col + 3];
                }
                *(float4*)(Crow + col) = r;
            }
        }
    }
}

// ---------------------------------------------------------------------------
// Windowed attention: one block per (batch, window, head). 128 threads.
// q/k/v gathered from g_qkv into smem, S=qk^T*scale, softmax, O=P@v -> g_y.
// ---------------------------------------------------------------------------
__global__ __launch_bounds__(128) void attn_kernel(
    const float* __restrict__ qkv, float* __restrict__ y)
{
    __shared__ float qs[WIN][HD];
    __shared__ float ks[WIN][HD];
    __shared__ float vs[WIN][HD];
    __shared__ float S[WIN][52];   // padded

    const int tid = threadIdx.x;
    int bwh = blockIdx.x;
    const int h = bwh % NHEADS; bwh /= NHEADS;
    const int w = bwh & 63;     const int b = bwh >> 6;
    const int hi = w >> 3, wi = w & 7;
    const int col0 = h * HD;

    // Gather q/k/v window tiles (float4 per thread item)
    for (int t = tid; t < WIN * 8; t += 128) {
        int row = t >> 3, q4 = (t & 7) << 2;
        int n = (hi * 7 + row / 7) * 56 + wi * 7 + (row % 7);
        const float* p = qkv + ((size_t)(b * NN + n)) * C3 + col0 + q4;
        float4 qv = *(const float4*)(p);
        float4 kv = *(const float4*)(p + CC);
        float4 vv = *(const float4*)(p + 2 * CC);
        *(float4*)&qs[row][q4] = qv;
        *(float4*)&ks[row][q4] = kv;
        *(float4*)&vs[row][q4] = vv;
    }
    __syncthreads();

    const float scale = 0.17677669529663687f;  // 32^-0.5
    for (int idx = tid; idx < WIN * WIN; idx += 128) {
        int i = idx / WIN, j = idx - i * WIN;
        float s = 0.f;
#pragma unroll
        for (int kk = 0; kk < 8; kk++) {
            float4 a = *(const float4*)&qs[i][kk * 4];
            float4 c = *(const float4*)&ks[j][kk * 4];
            s += a.x * c.x + a.y * c.y + a.z * c.z + a.w * c.w;
        }
        S[i][j] = s * scale;
    }
    __syncthreads();

    // Softmax: one warp per row (rows 0..48, strided by 4 warps)
    const int lane = tid & 31, warp = tid >> 5;
    for (int r = warp; r < WIN; r += 4) {
        float x1 = S[r][lane];
        float x2 = (lane + 32 < WIN) ? S[r][lane + 32] : -1e30f;
        float m = fmaxf(x1, x2);
#pragma unroll
        for (int o = 16; o; o >>= 1) m = fmaxf(m, __shfl_xor_sync(0xffffffffu, m, o));
        float e1 = __expf(x1 - m);
        float e2 = (lane + 32 < WIN) ? __expf(x2 - m) : 0.f;
        float ssum = e1 + e2;
#pragma unroll
        for (int o = 16; o; o >>= 1) ssum += __shfl_xor_sync(0xffffffffu, ssum, o);
        float inv = 1.f / ssum;
        S[r][lane] = e1 * inv;
        if (lane + 32 < WIN) S[r][lane + 32] = e2 * inv;
    }
    __syncthreads();

    // O = P @ V, write to y
    for (int idx = tid; idx < WIN * HD; idx += 128) {
        int i = idx >> 5, d = idx & 31;
        float o = 0.f;
#pragma unroll 7
        for (int j = 0; j < WIN; j++) o += S[i][j] * vs[j][d];
        int n = (hi * 7 + i / 7) * 56 + wi * 7 + (i % 7);
        y[((size_t)(b * NN + n)) * CC + col0 + d] = o;
    }
}

// ---------------------------------------------------------------------------
// Depthwise 3x3 conv (cross-correlation, SAME) on v + residual add into y
// ---------------------------------------------------------------------------
__global__ void conv_add_kernel(
    const float* __restrict__ qkv,
    const float* __restrict__ w_conv,
    const float* __restrict__ b_conv,
    float* __restrict__ y)
{
    int idx = blockIdx.x * blockDim.x + threadIdx.x;
    if (idx >= BATCH * NN * CC) return;
    int c = idx % CC;
    int n = (idx / CC) % NN;
    int b = idx / (CC * NN);
    int hh = n / WW, ww = n % WW;

    float acc = b_conv[c];
#pragma unroll
    for (int kh = 0; kh < 3; kh++) {
        int hn = hh + kh - 1;
        if ((unsigned)hn >= (unsigned)HH) continue;
#pragma unroll
        for (int kw = 0; kw < 3; kw++) {
            int wn = ww + kw - 1;
            if ((unsigned)wn >= (unsigned)WW) continue;
            acc += qkv[((size_t)(b * NN + hn * WW + wn)) * C3 + 2 * CC + c] *
                   __ldg(&w_conv[(kh * 3 + kw) * CC + c]);
        }
    }
    y[idx] += acc;
}

// ---------------------------------------------------------------------------
extern "C" void kernel_launch(void* const* d_in, const int* in_sizes, int n_in,
                              void* d_out, int out_size)
{
    const float* x      = (const float*)d_in[0];
    const float* w_qkv  = (const float*)d_in[1];
    const float* w_proj = (const float*)d_in[2];
    const float* b_proj = (const float*)d_in[3];
    const float* w_conv = (const float*)d_in[4];
    const float* b_conv = (const float*)d_in[5];
    float* out = (float*)d_out;

    float* qkv_p = nullptr;
    float* y_p = nullptr;
    cudaGetSymbolAddress((void**)&qkv_p, g_qkv);
    cudaGetSymbolAddress((void**)&y_p, g_y);

    // 1) qkv = x @ w_qkv   (50176 x 1152 x 384)
    {
        dim3 grid(C3 / 128, MROWS / 128);
        sgemm_kernel<<<grid, 256>>>(x, w_qkv, qkv_p, nullptr, MROWS, C3, CC);
    }
    // 2) windowed attention -> y
    {
        attn_kernel<<<BATCH * 64 * NHEADS, 128>>>(qkv_p, y_p);
    }
    // 3) y += depthwise_conv3x3(v) + b_conv
    {
        int total = BATCH * NN * CC;
        conv_add_kernel<<<(total + 255) / 256, 256>>>(qkv_p, w_conv, b_conv, y_p);
    }
    // 4) out = y @ w_proj + b_proj   (50176 x 384 x 384)
    {
        dim3 grid(CC / 128, MROWS / 128);
        sgemm_kernel<<<grid, 256>>>(y_p, w_proj, out, b_proj, MROWS, CC, CC);
    }
}

// round 3
// speedup vs baseline: 2.4069x; 2.4069x over previous
#include <cuda_runtime.h>
#include <cuda_bf16.h>
#include <cstdint>

// Problem constants
#define BATCH 16
#define HH 56
#define WW 56
#define NN (HH * WW)          // 3136
#define CC 384
#define C3 (3 * CC)           // 1152
#define NHEADS 12
#define HD 32
#define WSZ 7
#define WIN 49
#define MROWS (BATCH * NN)    // 50176

// GEMM tiling
#define BM 128
#define BN 128
#define BK 32
#define SROW 36               // smem row stride in floats (144B: 16B-aligned, conflict-free)
#define ABYTES (BM * SROW * 4)   // 18432 per buffer

// Scratch (allocation-free rule: __device__ globals)
__device__ float g_qkv[(size_t)MROWS * C3];     // 231 MB
__device__ float g_y[(size_t)MROWS * CC];       // 77 MB
__device__ float g_xr[(size_t)MROWS * CC];      // 77 MB (tf32-rounded x)
__device__ float g_wt1[(size_t)C3 * CC];        // w_qkv transposed [1152][384]
__device__ float g_wt2[(size_t)CC * CC];        // w_proj transposed [384][384]

// ---------------------------------------------------------------------------
__device__ __forceinline__ uint32_t smem_u32(const void* p) {
    uint32_t a;
    asm("{ .reg .u64 t; cvta.to.shared.u64 t, %1; cvt.u32.u64 %0, t; }" : "=r"(a) : "l"(p));
    return a;
}
__device__ __forceinline__ void cp_async16(uint32_t saddr, const void* gaddr) {
    asm volatile("cp.async.cg.shared.global [%0], [%1], 16;" :: "r"(saddr), "l"(gaddr));
}
__device__ __forceinline__ float round_tf32(float f) {
    uint32_t u;
    asm("cvt.rna.tf32.f32 %0, %1;" : "=r"(u) : "f"(f));
    return __uint_as_float(u);
}
__device__ __forceinline__ void mma_tf32(float c[4], const uint32_t a[4], const uint32_t b[2]) {
    asm volatile(
        "mma.sync.aligned.m16n8k8.row.col.f32.tf32.tf32.f32 "
        "{%0,%1,%2,%3}, {%4,%5,%6,%7}, {%8,%9}, {%0,%1,%2,%3};"
        : "+f"(c[0]), "+f"(c[1]), "+f"(c[2]), "+f"(c[3])
        : "r"(a[0]), "r"(a[1]), "r"(a[2]), "r"(a[3]), "r"(b[0]), "r"(b[1]));
}

// ---------------------------------------------------------------------------
// tf32 mma.sync GEMM: C[M,N] = A[M,K] @ Bt[N,K]^T (+bias)
// A row-major [M,K], Bt row-major [N,K], both tf32-rounded fp32.
// M%128==0, N%128==0, K%32==0.  256 threads, 8 warps (2m x 4n), 64x32/warp.
// Dynamic smem: As0, Bs0, As1, Bs1 — each [128][36] floats.
// ---------------------------------------------------------------------------
__global__ __launch_bounds__(256)
void gemm_tf32_kernel(const float* __restrict__ A, const float* __restrict__ Bt,
                      float* __restrict__ C, const float* __restrict__ bias,
                      int M, int N, int K)
{
    extern __shared__ float smem[];
    float* As[2] = { smem,                 smem + 2 * (ABYTES / 4) };
    float* Bs[2] = { smem + (ABYTES / 4),  smem + 3 * (ABYTES / 4) };
    const uint32_t sbase = smem_u32(smem);

    const int tid  = threadIdx.x;
    const int wid  = tid >> 5;
    const int lane = tid & 31;
    const int wm = (wid & 1) * 64;     // warp m offset within tile
    const int wn = (wid >> 1) * 32;    // warp n offset within tile
    const int qr = lane >> 2;          // quad row 0..7
    const int qc = lane & 3;           // quad col 0..3

    const int nbase = blockIdx.x * BN;
    const size_t mbase = (size_t)blockIdx.y * BM;

    const int row_ld = tid >> 1;            // 0..127  (2 threads per row)
    const int c4_ld  = (tid & 1) << 2;      // chunk 0 or 4 (of 8 16B-chunks)

    float acc[4][4][4];
    #pragma unroll
    for (int i = 0; i < 4; i++)
        #pragma unroll
        for (int j = 0; j < 4; j++)
            #pragma unroll
            for (int r = 0; r < 4; r++) acc[i][j][r] = 0.f;

    const int nstages = K / BK;

    auto load_stage = [&](int s) {
        const int buf = s & 1;
        const uint32_t a_s = sbase + (uint32_t)buf * 2u * ABYTES;
        const uint32_t b_s = a_s + ABYTES;
        const int k0 = s * BK;
        const float* Ag = A + (mbase + row_ld) * (size_t)K + k0;
        const float* Bg = Bt + (size_t)(nbase + row_ld) * K + k0;
        const uint32_t soff = (uint32_t)row_ld * (SROW * 4);
        #pragma unroll
        for (int cc = 0; cc < 4; cc++) {
            cp_async16(a_s + soff + ((c4_ld + cc) << 4), Ag + ((c4_ld + cc) << 2));
            cp_async16(b_s + soff + ((c4_ld + cc) << 4), Bg + ((c4_ld + cc) << 2));
        }
        asm volatile("cp.async.commit_group;");
    };

    load_stage(0);
    if (nstages > 1) load_stage(1);

    for (int s = 0; s < nstages; s++) {
        if (s + 1 < nstages) asm volatile("cp.async.wait_group 1;" ::: "memory");
        else                 asm volatile("cp.async.wait_group 0;" ::: "memory");
        __syncthreads();

        const float* Ab = As[s & 1];
        const float* Bb = Bs[s & 1];

        #pragma unroll
        for (int ks = 0; ks < 4; ks++) {
            const int k0 = ks * 8;
            uint32_t afr[4][4];
            uint32_t bfr[4][2];
            #pragma unroll
            for (int i = 0; i < 4; i++) {
                const float* ap = Ab + (wm + i * 16 + qr) * SROW + k0 + qc;
                afr[i][0] = __float_as_uint(ap[0]);
                afr[i][1] = __float_as_uint(ap[8 * SROW]);
                afr[i][2] = __float_as_uint(ap[4]);
                afr[i][3] = __float_as_uint(ap[8 * SROW + 4]);
            }
            #pragma unroll
            for (int j = 0; j < 4; j++) {
                const float* bp = Bb + (wn + j * 8 + qr) * SROW + k0 + qc;
                bfr[j][0] = __float_as_uint(bp[0]);
                bfr[j][1] = __float_as_uint(bp[4]);
            }
            #pragma unroll
            for (int i = 0; i < 4; i++)
                #pragma unroll
                for (int j = 0; j < 4; j++)
                    mma_tf32(acc[i][j], afr[i], bfr[j]);
        }
        __syncthreads();
        if (s + 2 < nstages) load_stage(s + 2);
    }

    // Epilogue: tile (i,j): rows mbase+wm+16i+qr (+8), cols nbase+wn+8j+2*qc (+1)
    #pragma unroll
    for (int i = 0; i < 4; i++) {
        float* Crow0 = C + (mbase + wm + i * 16 + qr) * (size_t)N + nbase + wn;
        float* Crow1 = Crow0 + 8 * (size_t)N;
        #pragma unroll
        for (int j = 0; j < 4; j++) {
            const int col = j * 8 + 2 * qc;
            float2 v0 = make_float2(acc[i][j][0], acc[i][j][1]);
            float2 v1 = make_float2(acc[i][j][2], acc[i][j][3]);
            if (bias) {
                float2 bb = *(const float2*)(bias + nbase + wn + col);
                v0.x += bb.x; v0.y += bb.y;
                v1.x += bb.x; v1.y += bb.y;
            }
            *(float2*)(Crow0 + col) = v0;
            *(float2*)(Crow1 + col) = v1;
        }
    }
}

// ---------------------------------------------------------------------------
// Elementwise tf32-RN rounding (float4 vectorized)
// ---------------------------------------------------------------------------
__global__ void round_tf32_kernel(const float* __restrict__ in, float* __restrict__ out, int n4)
{
    int i = blockIdx.x * blockDim.x + threadIdx.x;
    if (i >= n4) return;
    float4 v = ((const float4*)in)[i];
    v.x = round_tf32(v.x); v.y = round_tf32(v.y);
    v.z = round_tf32(v.z); v.w = round_tf32(v.w);
    ((float4*)out)[i] = v;
}

// Transpose + tf32 round: out[n*K + k] = rna(in[k*N + n]).  in: [K][N]
__global__ void transpose_round_kernel(const float* __restrict__ in, float* __restrict__ out,
                                       int K, int N)
{
    int i = blockIdx.x * blockDim.x + threadIdx.x;
    if (i >= K * N) return;
    int n = i % N, k = i / N;
    out[(size_t)n * K + k] = round_tf32(in[(size_t)k * N + n]);
}

// ---------------------------------------------------------------------------
// Windowed attention: one block per (batch, window, head), 64 threads,
// one thread per q-row. k/v in smem (broadcast reads), S in padded smem.
// ---------------------------------------------------------------------------
__global__ __launch_bounds__(64) void attn_kernel(
    const float* __restrict__ qkv, float* __restrict__ y)
{
    __shared__ float ks[WIN][HD];
    __shared__ float vs[WIN][HD];
    __shared__ float S[64][53];

    const int tid = threadIdx.x;
    int bwh = blockIdx.x;
    const int h = bwh % NHEADS; bwh /= NHEADS;
    const int w = bwh & 63; const int b = bwh >> 6;
    const int hi = w >> 3, wi = w & 7;
    const int col0 = h * HD;

    for (int t = tid; t < WIN * 8; t += 64) {
        int row = t >> 3, c4 = (t & 7) << 2;
        int n = (hi * 7 + row / 7) * 56 + wi * 7 + (row % 7);
        const float* p = qkv + ((size_t)(b * NN + n)) * C3 + col0 + c4;
        *(float4*)&ks[row][c4] = *(const float4*)(p + CC);
        *(float4*)&vs[row][c4] = *(const float4*)(p + 2 * CC);
    }

    const int i = tid;
    const bool active = (i < WIN);
    int n_i = 0;
    float q[HD];
    if (active) {
        n_i = (hi * 7 + i / 7) * 56 + wi * 7 + (i % 7);
        const float* p = qkv + ((size_t)(b * NN + n_i)) * C3 + col0;
        #pragma unroll
        for (int c4 = 0; c4 < 8; c4++) {
            float4 v = *(const float4*)(p + c4 * 4);
            q[c4 * 4 + 0] = v.x; q[c4 * 4 + 1] = v.y;
            q[c4 * 4 + 2] = v.z; q[c4 * 4 + 3] = v.w;
        }
    }
    __syncthreads();

    if (active) {
        const float scale = 0.17677669529663687f;  // 32^-0.5
        float m = -1e30f;
        #pragma unroll 4
        for (int j = 0; j < WIN; j++) {
            float acc = 0.f;
            #pragma unroll
            for (int c4 = 0; c4 < 8; c4++) {
                float4 kv = *(const float4*)&ks[j][c4 * 4];
                acc += q[c4 * 4 + 0] * kv.x + q[c4 * 4 + 1] * kv.y +
                       q[c4 * 4 + 2] * kv.z + q[c4 * 4 + 3] * kv.w;
            }
            acc *= scale;
            S[i][j] = acc;
            m = fmaxf(m, acc);
        }
        float sum = 0.f;
        #pragma unroll 4
        for (int j = 0; j < WIN; j++) {
            float e = __expf(S[i][j] - m);
            sum += e;
            S[i][j] = e;
        }
        const float inv = 1.f / sum;

        float o[HD];
        #pragma unroll
        for (int d = 0; d < HD; d++) o[d] = 0.f;
        #pragma unroll 4
        for (int j = 0; j < WIN; j++) {
            float pj = S[i][j] * inv;
            #pragma unroll
            for (int c4 = 0; c4 < 8; c4++) {
                float4 vv = *(const float4*)&vs[j][c4 * 4];
                o[c4 * 4 + 0] += pj * vv.x; o[c4 * 4 + 1] += pj * vv.y;
                o[c4 * 4 + 2] += pj * vv.z; o[c4 * 4 + 3] += pj * vv.w;
            }
        }
        float* yo = y + ((size_t)(b * NN + n_i)) * CC + col0;
        #pragma unroll
        for (int c4 = 0; c4 < 8; c4++) {
            float4 r;
            r.x = o[c4 * 4 + 0]; r.y = o[c4 * 4 + 1];
            r.z = o[c4 * 4 + 2]; r.w = o[c4 * 4 + 3];
            *(float4*)(yo + c4 * 4) = r;
        }
    }
}

// ---------------------------------------------------------------------------
// Depthwise 3x3 conv (SAME) on v + residual add into y, tf32-RN rounded output
// ---------------------------------------------------------------------------
__global__ void conv_add_kernel(
    const float* __restrict__ qkv,
    const float* __restrict__ w_conv,
    const float* __restrict__ b_conv,
    float* __restrict__ y)
{
    int idx = blockIdx.x * blockDim.x + threadIdx.x;
    if (idx >= BATCH * NN * CC) return;
    int c = idx % CC;
    int n = (idx / CC) % NN;
    int b = idx / (CC * NN);
    int hh = n / WW, ww = n % WW;

    float acc = b_conv[c];
    #pragma unroll
    for (int kh = 0; kh < 3; kh++) {
        int hn = hh + kh - 1;
        if ((unsigned)hn >= (unsigned)HH) continue;
        #pragma unroll
        for (int kw = 0; kw < 3; kw++) {
            int wn = ww + kw - 1;
            if ((unsigned)wn >= (unsigned)WW) continue;
            acc += qkv[((size_t)(b * NN + hn * WW + wn)) * C3 + 2 * CC + c] *
                   __ldg(&w_conv[(kh * 3 + kw) * CC + c]);
        }
    }
    y[idx] = round_tf32(y[idx] + acc);
}

// ---------------------------------------------------------------------------
extern "C" void kernel_launch(void* const* d_in, const int* in_sizes, int n_in,
                              void* d_out, int out_size)
{
    const float* x      = (const float*)d_in[0];
    const float* w_qkv  = (const float*)d_in[1];
    const float* w_proj = (const float*)d_in[2];
    const float* b_proj = (const float*)d_in[3];
    const float* w_conv = (const float*)d_in[4];
    const float* b_conv = (const float*)d_in[5];
    float* out = (float*)d_out;

    float *qkv_p, *y_p, *xr_p, *wt1_p, *wt2_p;
    cudaGetSymbolAddress((void**)&qkv_p, g_qkv);
    cudaGetSymbolAddress((void**)&y_p, g_y);
    cudaGetSymbolAddress((void**)&xr_p, g_xr);
    cudaGetSymbolAddress((void**)&wt1_p, g_wt1);
    cudaGetSymbolAddress((void**)&wt2_p, g_wt2);

    const int gemm_smem = 4 * ABYTES;  // 73728
    cudaFuncSetAttribute(gemm_tf32_kernel,
                         cudaFuncAttributeMaxDynamicSharedMemorySize, gemm_smem);

    // 0) tf32-RNA rounding of x + transposed/rounded weights
    {
        int n4 = MROWS * CC / 4;
        round_tf32_kernel<<<(n4 + 255) / 256, 256>>>(x, xr_p, n4);
        transpose_round_kernel<<<(CC * C3 + 255) / 256, 256>>>(w_qkv, wt1_p, CC, C3);
        transpose_round_kernel<<<(CC * CC + 255) / 256, 256>>>(w_proj, wt2_p, CC, CC);
    }
    // 1) qkv = x @ w_qkv   (50176 x 1152 x 384) via mma.sync tf32
    {
        dim3 grid(C3 / BN, MROWS / BM);
        gemm_tf32_kernel<<<grid, 256, gemm_smem>>>(xr_p, wt1_p, qkv_p, nullptr,
                                                   MROWS, C3, CC);
    }
    // 2) windowed attention -> y
    attn_kernel<<<BATCH * 64 * NHEADS, 64>>>(qkv_p, y_p);
    // 3) y = round_tf32(y + depthwise_conv3x3(v) + b_conv)
    {
        int total = BATCH * NN * CC;
        conv_add_kernel<<<(total + 255) / 256, 256>>>(qkv_p, w_conv, b_conv, y_p);
    }
    // 4) out = y @ w_proj + b_proj   (50176 x 384 x 384) via mma.sync tf32
    {
        dim3 grid(CC / BN, MROWS / BM);
        gemm_tf32_kernel<<<grid, 256, gemm_smem>>>(y_p, wt2_p, out, b_proj,
                                                   MROWS, CC, CC);
    }
}

// round 4
// speedup vs baseline: 2.8157x; 1.1698x over previous
#include <cuda_runtime.h>
#include <cuda_bf16.h>
#include <cstdint>

// Problem constants
#define BATCH 16
#define HH 56
#define WW 56
#define NN (HH * WW)          // 3136
#define CC 384
#define C3 (3 * CC)           // 1152
#define NHEADS 12
#define HD 32
#define WSZ 7
#define WIN 49
#define MROWS (BATCH * NN)    // 50176

// GEMM tiling
#define BM 128
#define BN 128
#define BK 32
#define SROW 36                   // smem row stride (floats); 144B = 9*16B, conflict-free
#define ABYTES (BM * SROW * 4)    // 18432 per A (or B) buffer
#define STAGE_BYTES (2 * ABYTES)  // 36864
#define NSTAGE 3

// Scratch (allocation-free rule: __device__ globals)
__device__ float g_qkv[(size_t)MROWS * C3];     // 231 MB
__device__ float g_y[(size_t)MROWS * CC];       // 77 MB
__device__ float g_xr[(size_t)MROWS * CC];      // 77 MB (tf32-rounded x)
__device__ float g_wt1[(size_t)C3 * CC];        // w_qkv transposed [1152][384]
__device__ float g_wt2[(size_t)CC * CC];        // w_proj transposed [384][384]

// ---------------------------------------------------------------------------
__device__ __forceinline__ uint32_t smem_u32(const void* p) {
    uint32_t a;
    asm("{ .reg .u64 t; cvta.to.shared.u64 t, %1; cvt.u32.u64 %0, t; }" : "=r"(a) : "l"(p));
    return a;
}
__device__ __forceinline__ void cp_async16(uint32_t saddr, const void* gaddr) {
    asm volatile("cp.async.cg.shared.global [%0], [%1], 16;" :: "r"(saddr), "l"(gaddr));
}
__device__ __forceinline__ float round_tf32(float f) {
    uint32_t u;
    asm("cvt.rna.tf32.f32 %0, %1;" : "=r"(u) : "f"(f));
    return __uint_as_float(u);
}
__device__ __forceinline__ void mma_tf32(float c[4], const uint32_t a[4],
                                         uint32_t b0, uint32_t b1) {
    asm volatile(
        "mma.sync.aligned.m16n8k8.row.col.f32.tf32.tf32.f32 "
        "{%0,%1,%2,%3}, {%4,%5,%6,%7}, {%8,%9}, {%0,%1,%2,%3};"
        : "+f"(c[0]), "+f"(c[1]), "+f"(c[2]), "+f"(c[3])
        : "r"(a[0]), "r"(a[1]), "r"(a[2]), "r"(a[3]), "r"(b0), "r"(b1));
}
__device__ __forceinline__ void ldm_x4(uint32_t r[4], uint32_t addr) {
    asm volatile("ldmatrix.sync.aligned.m8n8.x4.shared.b16 {%0,%1,%2,%3}, [%4];"
        : "=r"(r[0]), "=r"(r[1]), "=r"(r[2]), "=r"(r[3]) : "r"(addr));
}

// ---------------------------------------------------------------------------
// tf32 mma.sync GEMM: C[M,N] = A[M,K] @ Bt[N,K]^T (+bias)
// A row-major [M,K], Bt row-major [N,K], both tf32-rounded fp32.
// M%128==0, N%128==0, K%32==0.  256 threads, 8 warps (2m x 4n), 64x32/warp.
// 3-stage cp.async pipeline; fragments via ldmatrix (b32-as-b16 trick).
// ---------------------------------------------------------------------------
__global__ __launch_bounds__(256)
void gemm_tf32_kernel(const float* __restrict__ A, const float* __restrict__ Bt,
                      float* __restrict__ C, const float* __restrict__ bias,
                      int M, int N, int K)
{
    extern __shared__ float smem[];
    const uint32_t sbase = smem_u32(smem);

    const int tid  = threadIdx.x;
    const int wid  = tid >> 5;
    const int lane = tid & 31;
    const int wm = (wid & 1) * 64;     // warp m offset
    const int wn = (wid >> 1) * 32;    // warp n offset
    const int qr = lane >> 2;          // 0..7
    const int qc = lane & 3;           // 0..3

    const int nbase = blockIdx.x * BN;
    const size_t mbase = (size_t)blockIdx.y * BM;

    const int row_ld = tid >> 1;            // 0..127
    const int c4_ld  = (tid & 1) << 2;      // 16B-chunk 0 or 4

    // ldmatrix per-lane addresses (offsets within a stage buffer)
    const int r8  = lane & 7;
    const int sel = lane >> 3;
    uint32_t a_off[4], b_off[2];
    #pragma unroll
    for (int i = 0; i < 4; i++)
        a_off[i] = (uint32_t)((wm + 16 * i + ((sel & 1) << 3) + r8) * SROW) * 4u
                 + ((uint32_t)(sel >> 1) << 4);
    #pragma unroll
    for (int p = 0; p < 2; p++)
        b_off[p] = (uint32_t)ABYTES
                 + (uint32_t)((wn + 16 * p + ((sel >> 1) << 3) + r8) * SROW) * 4u
                 + ((uint32_t)(sel & 1) << 4);

    float acc[4][4][4];
    #pragma unroll
    for (int i = 0; i < 4; i++)
        #pragma unroll
        for (int j = 0; j < 4; j++)
            #pragma unroll
            for (int t = 0; t < 4; t++) acc[i][j][t] = 0.f;

    const int nstages = K / BK;

    auto load_stage = [&](int s) {
        const uint32_t base = sbase + (uint32_t)(s % NSTAGE) * STAGE_BYTES;
        const int k0 = s * BK;
        const float* Ag = A + (mbase + row_ld) * (size_t)K + k0;
        const float* Bg = Bt + (size_t)(nbase + row_ld) * K + k0;
        const uint32_t soff = (uint32_t)row_ld * (SROW * 4);
        #pragma unroll
        for (int cc = 0; cc < 4; cc++) {
            cp_async16(base + soff + ((c4_ld + cc) << 4), Ag + ((c4_ld + cc) << 2));
            cp_async16(base + ABYTES + soff + ((c4_ld + cc) << 4), Bg + ((c4_ld + cc) << 2));
        }
        asm volatile("cp.async.commit_group;");
    };

    load_stage(0);
    load_stage(1);

    for (int s = 0; s < nstages; s++) {
        if (s + 1 < nstages) asm volatile("cp.async.wait_group 1;" ::: "memory");
        else                 asm volatile("cp.async.wait_group 0;" ::: "memory");
        __syncthreads();
        if (s + 2 < nstages) load_stage(s + 2);

        const uint32_t sstage = sbase + (uint32_t)(s % NSTAGE) * STAGE_BYTES;
        #pragma unroll
        for (int ks = 0; ks < 4; ks++) {
            const uint32_t kb = (uint32_t)ks << 5;   // ks * 32 bytes
            uint32_t afr[4][4];
            uint32_t bfr[2][4];
            #pragma unroll
            for (int i = 0; i < 4; i++) ldm_x4(afr[i], sstage + a_off[i] + kb);
            #pragma unroll
            for (int p = 0; p < 2; p++) ldm_x4(bfr[p], sstage + b_off[p] + kb);
            #pragma unroll
            for (int i = 0; i < 4; i++)
                #pragma unroll
                for (int j = 0; j < 4; j++)
                    mma_tf32(acc[i][j], afr[i], bfr[j >> 1][(j & 1) * 2],
                             bfr[j >> 1][(j & 1) * 2 + 1]);
        }
    }

    // Epilogue
    #pragma unroll
    for (int i = 0; i < 4; i++) {
        float* Crow0 = C + (mbase + wm + i * 16 + qr) * (size_t)N + nbase + wn;
        float* Crow1 = Crow0 + 8 * (size_t)N;
        #pragma unroll
        for (int j = 0; j < 4; j++) {
            const int col = j * 8 + 2 * qc;
            float2 v0 = make_float2(acc[i][j][0], acc[i][j][1]);
            float2 v1 = make_float2(acc[i][j][2], acc[i][j][3]);
            if (bias) {
                float2 bb = *(const float2*)(bias + nbase + wn + col);
                v0.x += bb.x; v0.y += bb.y;
                v1.x += bb.x; v1.y += bb.y;
            }
            *(float2*)(Crow0 + col) = v0;
            *(float2*)(Crow1 + col) = v1;
        }
    }
}

// ---------------------------------------------------------------------------
__global__ void round_tf32_kernel(const float* __restrict__ in, float* __restrict__ out, int n4)
{
    int i = blockIdx.x * blockDim.x + threadIdx.x;
    if (i >= n4) return;
    float4 v = ((const float4*)in)[i];
    v.x = round_tf32(v.x); v.y = round_tf32(v.y);
    v.z = round_tf32(v.z); v.w = round_tf32(v.w);
    ((float4*)out)[i] = v;
}

// Transpose + tf32 round: out[n*K + k] = rna(in[k*N + n]).  in: [K][N]
__global__ void transpose_round_kernel(const float* __restrict__ in, float* __restrict__ out,
                                       int K, int N)
{
    int i = blockIdx.x * blockDim.x + threadIdx.x;
    if (i >= K * N) return;
    int n = i % N, k = i / N;
    out[(size_t)n * K + k] = round_tf32(in[(size_t)k * N + n]);
}

// ---------------------------------------------------------------------------
// Windowed attention: one block per (batch, window, head), 64 threads,
// one thread per q-row. k/v in smem (broadcast reads), S in padded smem.
// ---------------------------------------------------------------------------
__global__ __launch_bounds__(64) void attn_kernel(
    const float* __restrict__ qkv, float* __restrict__ y)
{
    __shared__ float ks[WIN][HD];
    __shared__ float vs[WIN][HD];
    __shared__ float S[64][53];

    const int tid = threadIdx.x;
    int bwh = blockIdx.x;
    const int h = bwh % NHEADS; bwh /= NHEADS;
    const int w = bwh & 63; const int b = bwh >> 6;
    const int hi = w >> 3, wi = w & 7;
    const int col0 = h * HD;

    for (int t = tid; t < WIN * 8; t += 64) {
        int row = t >> 3, c4 = (t & 7) << 2;
        int n = (hi * 7 + row / 7) * 56 + wi * 7 + (row % 7);
        const float* p = qkv + ((size_t)(b * NN + n)) * C3 + col0 + c4;
        *(float4*)&ks[row][c4] = *(const float4*)(p + CC);
        *(float4*)&vs[row][c4] = *(const float4*)(p + 2 * CC);
    }

    const int i = tid;
    const bool active = (i < WIN);
    int n_i = 0;
    float q[HD];
    if (active) {
        n_i = (hi * 7 + i / 7) * 56 + wi * 7 + (i % 7);
        const float* p = qkv + ((size_t)(b * NN + n_i)) * C3 + col0;
        #pragma unroll
        for (int c4 = 0; c4 < 8; c4++) {
            float4 v = *(const float4*)(p + c4 * 4);
            q[c4 * 4 + 0] = v.x; q[c4 * 4 + 1] = v.y;
            q[c4 * 4 + 2] = v.z; q[c4 * 4 + 3] = v.w;
        }
    }
    __syncthreads();

    if (active) {
        const float scale = 0.17677669529663687f;  // 32^-0.5
        float m = -1e30f;
        #pragma unroll 4
        for (int j = 0; j < WIN; j++) {
            float acc = 0.f;
            #pragma unroll
            for (int c4 = 0; c4 < 8; c4++) {
                float4 kv = *(const float4*)&ks[j][c4 * 4];
                acc += q[c4 * 4 + 0] * kv.x + q[c4 * 4 + 1] * kv.y +
                       q[c4 * 4 + 2] * kv.z + q[c4 * 4 + 3] * kv.w;
            }
            acc *= scale;
            S[i][j] = acc;
            m = fmaxf(m, acc);
        }
        float sum = 0.f;
        #pragma unroll 4
        for (int j = 0; j < WIN; j++) {
            float e = __expf(S[i][j] - m);
            sum += e;
            S[i][j] = e;
        }
        const float inv = 1.f / sum;

        float o[HD];
        #pragma unroll
        for (int d = 0; d < HD; d++) o[d] = 0.f;
        #pragma unroll 4
        for (int j = 0; j < WIN; j++) {
            float pj = S[i][j] * inv;
            #pragma unroll
            for (int c4 = 0; c4 < 8; c4++) {
                float4 vv = *(const float4*)&vs[j][c4 * 4];
                o[c4 * 4 + 0] += pj * vv.x; o[c4 * 4 + 1] += pj * vv.y;
                o[c4 * 4 + 2] += pj * vv.z; o[c4 * 4 + 3] += pj * vv.w;
            }
        }
        float* yo = y + ((size_t)(b * NN + n_i)) * CC + col0;
        #pragma unroll
        for (int c4 = 0; c4 < 8; c4++) {
            float4 r;
            r.x = o[c4 * 4 + 0]; r.y = o[c4 * 4 + 1];
            r.z = o[c4 * 4 + 2]; r.w = o[c4 * 4 + 3];
            *(float4*)(yo + c4 * 4) = r;
        }
    }
}

// ---------------------------------------------------------------------------
// Depthwise 3x3 conv (SAME) on v + residual add into y, float4 per thread.
// ---------------------------------------------------------------------------
__global__ void conv_add_kernel(
    const float* __restrict__ qkv,
    const float* __restrict__ w_conv,
    const float* __restrict__ b_conv,
    float* __restrict__ y)
{
    const int C4 = CC / 4;
    int idx = blockIdx.x * blockDim.x + threadIdx.x;
    if (idx >= BATCH * NN * C4) return;
    int c4 = idx % C4;
    int n = (idx / C4) % NN;
    int b = idx / (C4 * NN);
    int hh = n / WW, ww = n % WW;
    const int c = c4 * 4;

    float4 acc = *(const float4*)(b_conv + c);
    #pragma unroll
    for (int kh = 0; kh < 3; kh++) {
        int hn = hh + kh - 1;
        if ((unsigned)hn >= (unsigned)HH) continue;
        #pragma unroll
        for (int kw = 0; kw < 3; kw++) {
            int wn = ww + kw - 1;
            if ((unsigned)wn >= (unsigned)WW) continue;
            float4 v = *(const float4*)(qkv + ((size_t)(b * NN + hn * WW + wn)) * C3 + 2 * CC + c);
            float4 wv = *(const float4*)(w_conv + (kh * 3 + kw) * CC + c);
            acc.x += v.x * wv.x; acc.y += v.y * wv.y;
            acc.z += v.z * wv.z; acc.w += v.w * wv.w;
        }
    }
    float4 yv = *(float4*)(y + (size_t)idx * 4);
    yv.x = round_tf32(yv.x + acc.x);
    yv.y = round_tf32(yv.y + acc.y);
    yv.z = round_tf32(yv.z + acc.z);
    yv.w = round_tf32(yv.w + acc.w);
    *(float4*)(y + (size_t)idx * 4) = yv;
}

// ---------------------------------------------------------------------------
extern "C" void kernel_launch(void* const* d_in, const int* in_sizes, int n_in,
                              void* d_out, int out_size)
{
    const float* x      = (const float*)d_in[0];
    const float* w_qkv  = (const float*)d_in[1];
    const float* w_proj = (const float*)d_in[2];
    const float* b_proj = (const float*)d_in[3];
    const float* w_conv = (const float*)d_in[4];
    const float* b_conv = (const float*)d_in[5];
    float* out = (float*)d_out;

    float *qkv_p, *y_p, *xr_p, *wt1_p, *wt2_p;
    cudaGetSymbolAddress((void**)&qkv_p, g_qkv);
    cudaGetSymbolAddress((void**)&y_p, g_y);
    cudaGetSymbolAddress((void**)&xr_p, g_xr);
    cudaGetSymbolAddress((void**)&wt1_p, g_wt1);
    cudaGetSymbolAddress((void**)&wt2_p, g_wt2);

    const int gemm_smem = NSTAGE * STAGE_BYTES;  // 110592
    cudaFuncSetAttribute(gemm_tf32_kernel,
                         cudaFuncAttributeMaxDynamicSharedMemorySize, gemm_smem);

    // 0) tf32-RNA rounding of x + transposed/rounded weights
    {
        int n4 = MROWS * CC / 4;
        round_tf32_kernel<<<(n4 + 255) / 256, 256>>>(x, xr_p, n4);
        transpose_round_kernel<<<(CC * C3 + 255) / 256, 256>>>(w_qkv, wt1_p, CC, C3);
        transpose_round_kernel<<<(CC * CC + 255) / 256, 256>>>(w_proj, wt2_p, CC, CC);
    }
    // 1) qkv = x @ w_qkv   (50176 x 1152 x 384) via mma.sync tf32
    {
        dim3 grid(C3 / BN, MROWS / BM);
        gemm_tf32_kernel<<<grid, 256, gemm_smem>>>(xr_p, wt1_p, qkv_p, nullptr,
                                                   MROWS, C3, CC);
    }
    // 2) windowed attention -> y
    attn_kernel<<<BATCH * 64 * NHEADS, 64>>>(qkv_p, y_p);
    // 3) y = round_tf32(y + depthwise_conv3x3(v) + b_conv)
    {
        int total = BATCH * NN * (CC / 4);
        conv_add_kernel<<<(total + 255) / 256, 256>>>(qkv_p, w_conv, b_conv, y_p);
    }
    // 4) out = y @ w_proj + b_proj   (50176 x 384 x 384) via mma.sync tf32
    {
        dim3 grid(CC / BN, MROWS / BM);
        gemm_tf32_kernel<<<grid, 256, gemm_smem>>>(y_p, wt2_p, out, b_proj,
                                                   MROWS, CC, CC);
    }
}